// round 7
// baseline (speedup 1.0000x reference)
#include <cuda_runtime.h>
#include <cuda_fp16.h>

#define BATCH 128
#define NTF 1024
#define NGENES 20000
#define NEDGE1 (NGENES * 64)     // 1,280,000 layer-1 edges
#define NW2 (NGENES * 16)        // 320,000 layer-2 weights
#define CHUNK 64                 // batch elements per block
#define NCHUNK 2
#define THREADS 1024             // 32 warps
#define GRID 148                 // one wave, 74 blocks per chunk
#define SMEM_BYTES (NTF * CHUNK * 2)  // 131072

// device scratch
__device__ __half g_xTh[NTF * BATCH];       // transposed fp16 features
__device__ unsigned int g_offs[NEDGE1];     // in1 * 128 (smem byte offsets)
__device__ __half g_w1h[NEDGE1];            // fp16 layer-1 weights
__device__ __half g_w2h[NW2];               // fp16 layer-2 weights
__device__ float  g_yT[NGENES * BATCH];     // gene-major output
__device__ unsigned int g_ticket[NCHUNK];

__device__ __forceinline__ unsigned int packh2(float a, float b) {
    const __half2 h = __float22half2_rn(make_float2(a, b));
    return *reinterpret_cast<const unsigned int*>(&h);
}

// prep: [0,128) feature transpose + ticket reset; [128,753) edge tables; [753,910) w2 table
__global__ void prep_kernel(const float* __restrict__ f,
                            const float* __restrict__ w1,
                            const int*   __restrict__ in1,
                            const float* __restrict__ w2) {
    const int bid = blockIdx.x;
    if (bid < 128) {
        __shared__ float tile[32][33];
        const int tx = threadIdx.x & 31, ty = threadIdx.x >> 5;
        const int t0 = (bid & 31) * 32;   // TF base
        const int b0 = (bid >> 5) * 32;   // batch base
#pragma unroll
        for (int j = 0; j < 32; j += 8)
            tile[ty + j][tx] = f[(b0 + ty + j) * NTF + t0 + tx];
        __syncthreads();
#pragma unroll
        for (int j = 0; j < 32; j += 8)
            g_xTh[(t0 + ty + j) * BATCH + b0 + tx] = __float2half(tile[tx][ty + j]);
        if (bid == 0 && threadIdx.x < NCHUNK)
            g_ticket[threadIdx.x] = 0u;
    } else if (bid < 128 + 625) {
        // 625*256*8 = 1,280,000 = NEDGE1 exactly
        const int e = ((bid - 128) * 256 + threadIdx.x) * 8;
        const int4 i0 = __ldg((const int4*)(in1 + e));
        const int4 i1 = __ldg((const int4*)(in1 + e) + 1);
        const float4 a = __ldg((const float4*)(w1 + e));
        const float4 b = __ldg((const float4*)(w1 + e) + 1);
        uint4 o0, o1;
        o0.x = (unsigned)i0.x << 7; o0.y = (unsigned)i0.y << 7;
        o0.z = (unsigned)i0.z << 7; o0.w = (unsigned)i0.w << 7;
        o1.x = (unsigned)i1.x << 7; o1.y = (unsigned)i1.y << 7;
        o1.z = (unsigned)i1.z << 7; o1.w = (unsigned)i1.w << 7;
        *(uint4*)(g_offs + e) = o0;
        *(uint4*)(g_offs + e + 4) = o1;
        uint4 wv;
        wv.x = packh2(a.x, a.y); wv.y = packh2(a.z, a.w);
        wv.z = packh2(b.x, b.y); wv.w = packh2(b.z, b.w);
        *(uint4*)(g_w1h + e) = wv;
    } else {
        // w2: 40000 threads x 8 = 320,000 = NW2
        const int e = ((bid - 753) * 256 + threadIdx.x) * 8;
        if (e < NW2) {
            const float4 a = __ldg((const float4*)(w2 + e));
            const float4 b = __ldg((const float4*)(w2 + e) + 1);
            uint4 wv;
            wv.x = packh2(a.x, a.y); wv.y = packh2(a.z, a.w);
            wv.z = packh2(b.x, b.y); wv.w = packh2(b.z, b.w);
            *(uint4*)(g_w2h + e) = wv;
        }
    }
}

// g_yT [NGENES][BATCH] -> out [BATCH][NGENES]
__global__ void transpose_out(float* __restrict__ out) {
    __shared__ float tile[32][33];
    const int tx = threadIdx.x, ty = threadIdx.y;
    const int g0 = blockIdx.x * 32;
    const int b0 = blockIdx.y * 32;
#pragma unroll
    for (int j = 0; j < 32; j += 8)
        tile[ty + j][tx] = g_yT[(g0 + ty + j) * BATCH + b0 + tx];
    __syncthreads();
#pragma unroll
    for (int j = 0; j < 32; j += 8)
        out[(b0 + ty + j) * NGENES + g0 + tx] = tile[tx][ty + j];
}

__device__ __forceinline__ __half2 u2h(unsigned int u) {
    return *reinterpret_cast<__half2*>(&u);
}

__device__ __forceinline__ float tanh_mufu(float x) {
    float y;
    asm("tanh.approx.f32 %0, %1;" : "=f"(y) : "f"(x));
    return y;
}

__device__ __forceinline__ __half2 tanh_h2(float2 a) {
    __half2 h = __float22half2_rn(a);
    unsigned int u = *reinterpret_cast<unsigned int*>(&h), r;
    asm("tanh.approx.f16x2 %0, %1;" : "=r"(r) : "r"(u));
    return u2h(r);
}

// 4 edges: gather 4 conflict-free rows, fp16 chain, fp32 accumulate
__device__ __forceinline__ void edge_group(const char* fb, uint4 o,
                                           unsigned int wlo, unsigned int whi,
                                           float2& acc) {
    const unsigned int x0 = *(const unsigned int*)(fb + o.x);
    const unsigned int x1 = *(const unsigned int*)(fb + o.y);
    const unsigned int x2 = *(const unsigned int*)(fb + o.z);
    const unsigned int x3 = *(const unsigned int*)(fb + o.w);
    __half2 c = __hmul2(__low2half2(u2h(wlo)),  u2h(x0));
    c = __hfma2(__high2half2(u2h(wlo)), u2h(x1), c);
    c = __hfma2(__low2half2(u2h(whi)),  u2h(x2), c);
    c = __hfma2(__high2half2(u2h(whi)), u2h(x3), c);
    const float2 cf = __half22float2(c);
    acc.x += cf.x; acc.y += cf.y;
}

// layer2 node o in fp16 + fp32 tanh + fp32 layer-3 accumulate
__device__ __forceinline__ void l23_node(const __half2* h1, unsigned int wlo,
                                         unsigned int whi, float b2o, float w3o,
                                         float2& y) {
    __half2 s = __half2half2(__float2half(b2o));
    s = __hfma2(__low2half2(u2h(wlo)),  h1[0], s);
    s = __hfma2(__high2half2(u2h(wlo)), h1[1], s);
    s = __hfma2(__low2half2(u2h(whi)),  h1[2], s);
    s = __hfma2(__high2half2(u2h(whi)), h1[3], s);
    const float2 sf = __half22float2(s);
    y.x = fmaf(w3o, tanh_mufu(sf.x), y.x);
    y.y = fmaf(w3o, tanh_mufu(sf.y), y.y);
}

__global__ void __launch_bounds__(THREADS, 1) fused_kernel(
    const float* __restrict__ b1, const float* __restrict__ b2,
    const float* __restrict__ w3, const float* __restrict__ b3)
{
    extern __shared__ unsigned int xs[];   // [NTF][32] uint -> 128B fp16 rows
    const int tid = threadIdx.x;
    const int chunk = blockIdx.x & 1;      // 148 blocks -> 74 per chunk
    const int b0 = chunk * CHUNK;

    // fill feature slice (rows of 64 fp16 = 8 uint4)
    {
        const uint4* src = (const uint4*)g_xTh;  // global row = 16 uint4
        uint4* dst = (uint4*)xs;
#pragma unroll
        for (int i = tid; i < NTF * 8; i += THREADS) {
            const int t = i >> 3, c = i & 7;
            dst[i] = src[t * 16 + chunk * 8 + c];
        }
    }
    __syncthreads();

    const int lane = tid & 31;
    const char* fb = (const char*)xs + lane * 4;   // lane's 2-batch column

    int cur = 0;
    if (lane == 0) cur = (int)atomicAdd(&g_ticket[chunk], 1u);
    cur = __shfl_sync(0xffffffffu, cur, 0);

    while (cur < NGENES) {
        // prefetch next ticket (hides ATOMG latency behind compute)
        int nxt = 0;
        if (lane == 0) nxt = (int)atomicAdd(&g_ticket[chunk], 1u);
        nxt = __shfl_sync(0xffffffffu, nxt, 0);

        const int g = cur;

        // ---------------- layer 1: 4 nodes x 16 edges ----------------
        __half2 h1[4];
        const float4 b1v = __ldg((const float4*)(b1 + g * 4));
        const float bn[4] = {b1v.x, b1v.y, b1v.z, b1v.w};
#pragma unroll
        for (int n = 0; n < 4; n++) {
            const uint4* onp = (const uint4*)(g_offs + g * 64 + n * 16);
            const uint4* wnp = (const uint4*)(g_w1h + g * 64 + n * 16);
            const uint4 oa = __ldg(onp);
            const uint4 ob = __ldg(onp + 1);
            const uint4 oc = __ldg(onp + 2);
            const uint4 od = __ldg(onp + 3);
            const uint4 wa = __ldg(wnp);
            const uint4 wb = __ldg(wnp + 1);
            float2 acc = make_float2(bn[n], bn[n]);
            edge_group(fb, oa, wa.x, wa.y, acc);
            edge_group(fb, ob, wa.z, wa.w, acc);
            edge_group(fb, oc, wb.x, wb.y, acc);
            edge_group(fb, od, wb.z, wb.w, acc);
            h1[n] = tanh_h2(acc);
        }

        // ---------------- layers 2+3 ----------------
        const uint4 w2v = __ldg((const uint4*)(g_w2h + g * 16));  // 16 halves? no: 8
        const uint4 w2u = __ldg((const uint4*)(g_w2h + g * 16) + 1);
        const float4 b2v = __ldg((const float4*)(b2 + g * 4));
        const float4 w3v = __ldg((const float4*)(w3 + g * 4));
        const float  yb  = __ldg(b3 + g);
        float2 y = make_float2(yb, yb);
        l23_node(h1, w2v.x, w2v.y, b2v.x, w3v.x, y);
        l23_node(h1, w2v.z, w2v.w, b2v.y, w3v.y, y);
        l23_node(h1, w2u.x, w2u.y, b2v.z, w3v.z, y);
        l23_node(h1, w2u.z, w2u.w, b2v.w, w3v.w, y);

        // coalesced gene-major store (float2 per lane, 256B per warp)
        *(float2*)&g_yT[g * BATCH + b0 + lane * 2] = y;

        cur = nxt;
    }
}

extern "C" void kernel_launch(void* const* d_in, const int* in_sizes, int n_in,
                              void* d_out, int out_size) {
    const float* features = (const float*)d_in[0];
    const float* w1 = (const float*)d_in[1];
    const float* b1 = (const float*)d_in[2];
    const float* w2 = (const float*)d_in[3];
    const float* b2 = (const float*)d_in[4];
    const float* w3 = (const float*)d_in[5];
    const float* b3 = (const float*)d_in[6];
    const int* in1 = (const int*)d_in[8];
    float* out = (float*)d_out;

    cudaFuncSetAttribute(fused_kernel,
                         cudaFuncAttributeMaxDynamicSharedMemorySize, SMEM_BYTES);

    prep_kernel<<<910, 256>>>(features, w1, in1, w2);
    fused_kernel<<<GRID, THREADS, SMEM_BYTES>>>(b1, b2, w3, b3);
    transpose_out<<<dim3(NGENES / 32, BATCH / 32), dim3(32, 8)>>>(out);
}

// round 8
// speedup vs baseline: 1.0422x; 1.0422x over previous
#include <cuda_runtime.h>
#include <cuda_fp16.h>

#define BATCH 128
#define NTF 1024
#define NGENES 20000
#define NEDGE1 (NGENES * 64)     // 1,280,000 layer-1 edges
#define NW2 (NGENES * 16)        // 320,000 layer-2 weights
#define CHUNK 64                 // batch elements per block
#define THREADS 1024             // 32 warps
#define GRID 148                 // one wave, 74 blocks per chunk
#define WARPS_PER_CHUNK 2368     // 74 blocks * 32 warps
#define SMEM_BYTES (NTF * CHUNK * 2)  // 131072

// device scratch
__device__ __half g_xTh[NTF * BATCH];       // transposed fp16 features
__device__ __half g_w1h[NEDGE1];            // fp16 layer-1 weights
__device__ __half g_w2h[NW2];               // fp16 layer-2 weights
__device__ float  g_yT[NGENES * BATCH];     // gene-major output

__device__ __forceinline__ unsigned int packh2(float a, float b) {
    const __half2 h = __float22half2_rn(make_float2(a, b));
    return *reinterpret_cast<const unsigned int*>(&h);
}

// prep: [0,128) feature transpose; [128,753) w1 fp16; [753,910) w2 fp16
__global__ void prep_kernel(const float* __restrict__ f,
                            const float* __restrict__ w1,
                            const float* __restrict__ w2) {
    const int bid = blockIdx.x;
    if (bid < 128) {
        __shared__ float tile[32][33];
        const int tx = threadIdx.x & 31, ty = threadIdx.x >> 5;
        const int t0 = (bid & 31) * 32;   // TF base
        const int b0 = (bid >> 5) * 32;   // batch base
#pragma unroll
        for (int j = 0; j < 32; j += 8)
            tile[ty + j][tx] = f[(b0 + ty + j) * NTF + t0 + tx];
        __syncthreads();
#pragma unroll
        for (int j = 0; j < 32; j += 8)
            g_xTh[(t0 + ty + j) * BATCH + b0 + tx] = __float2half(tile[tx][ty + j]);
    } else if (bid < 128 + 625) {
        // 625*256*8 = 1,280,000 = NEDGE1 exactly
        const int e = ((bid - 128) * 256 + threadIdx.x) * 8;
        const float4 a = __ldg((const float4*)(w1 + e));
        const float4 b = __ldg((const float4*)(w1 + e) + 1);
        uint4 wv;
        wv.x = packh2(a.x, a.y); wv.y = packh2(a.z, a.w);
        wv.z = packh2(b.x, b.y); wv.w = packh2(b.z, b.w);
        *(uint4*)(g_w1h + e) = wv;
    } else {
        // w2: 40000 threads x 8 = 320,000 = NW2
        const int e = ((bid - 753) * 256 + threadIdx.x) * 8;
        if (e < NW2) {
            const float4 a = __ldg((const float4*)(w2 + e));
            const float4 b = __ldg((const float4*)(w2 + e) + 1);
            uint4 wv;
            wv.x = packh2(a.x, a.y); wv.y = packh2(a.z, a.w);
            wv.z = packh2(b.x, b.y); wv.w = packh2(b.z, b.w);
            *(uint4*)(g_w2h + e) = wv;
        }
    }
}

// g_yT [NGENES][BATCH] -> out [BATCH][NGENES]
__global__ void transpose_out(float* __restrict__ out) {
    __shared__ float tile[32][33];
    const int tx = threadIdx.x, ty = threadIdx.y;
    const int g0 = blockIdx.x * 32;
    const int b0 = blockIdx.y * 32;
#pragma unroll
    for (int j = 0; j < 32; j += 8)
        tile[ty + j][tx] = g_yT[(g0 + ty + j) * BATCH + b0 + tx];
    __syncthreads();
#pragma unroll
    for (int j = 0; j < 32; j += 8)
        out[(b0 + ty + j) * NGENES + g0 + tx] = tile[tx][ty + j];
}

__device__ __forceinline__ __half2 u2h(unsigned int u) {
    return *reinterpret_cast<__half2*>(&u);
}

__device__ __forceinline__ float tanh_mufu(float x) {
    float y;
    asm("tanh.approx.f32 %0, %1;" : "=f"(y) : "f"(x));
    return y;
}

__device__ __forceinline__ __half2 tanh_h2(float2 a) {
    __half2 h = __float22half2_rn(a);
    unsigned int u = *reinterpret_cast<unsigned int*>(&h), r;
    asm("tanh.approx.f16x2 %0, %1;" : "=r"(r) : "r"(u));
    return u2h(r);
}

// 4 edges: 4 conflict-free row gathers (1 wavefront each), fp16 chain, fp32 acc
__device__ __forceinline__ void edge_group(const char* fb, int4 iv,
                                           unsigned int wlo, unsigned int whi,
                                           float2& acc) {
    const unsigned int x0 = *(const unsigned int*)(fb + iv.x * 128);
    const unsigned int x1 = *(const unsigned int*)(fb + iv.y * 128);
    const unsigned int x2 = *(const unsigned int*)(fb + iv.z * 128);
    const unsigned int x3 = *(const unsigned int*)(fb + iv.w * 128);
    __half2 c = __hmul2(__low2half2(u2h(wlo)),  u2h(x0));
    c = __hfma2(__high2half2(u2h(wlo)), u2h(x1), c);
    c = __hfma2(__low2half2(u2h(whi)),  u2h(x2), c);
    c = __hfma2(__high2half2(u2h(whi)), u2h(x3), c);
    const float2 cf = __half22float2(c);
    acc.x += cf.x; acc.y += cf.y;
}

// layer-2 node in fp16 + fp32 tanh + fp32 layer-3 accumulate
__device__ __forceinline__ void l23_node(const __half2* h1, unsigned int wlo,
                                         unsigned int whi, float b2o, float w3o,
                                         float2& y) {
    __half2 s = __half2half2(__float2half(b2o));
    s = __hfma2(__low2half2(u2h(wlo)),  h1[0], s);
    s = __hfma2(__high2half2(u2h(wlo)), h1[1], s);
    s = __hfma2(__low2half2(u2h(whi)),  h1[2], s);
    s = __hfma2(__high2half2(u2h(whi)), h1[3], s);
    const float2 sf = __half22float2(s);
    y.x = fmaf(w3o, tanh_mufu(sf.x), y.x);
    y.y = fmaf(w3o, tanh_mufu(sf.y), y.y);
}

__global__ void __launch_bounds__(THREADS, 1) fused_kernel(
    const int*   __restrict__ in1,
    const float* __restrict__ b1, const float* __restrict__ b2,
    const float* __restrict__ w3, const float* __restrict__ b3)
{
    extern __shared__ unsigned int xs[];   // [NTF][32] uint -> 128B fp16 rows
    const int tid = threadIdx.x;
    const int chunk = blockIdx.x & 1;      // 148 blocks -> 74 per chunk
    const int b0 = chunk * CHUNK;

    // fill feature slice (rows of 64 fp16 = 8 uint4)
    {
        const uint4* src = (const uint4*)g_xTh;  // global row = 16 uint4
        uint4* dst = (uint4*)xs;
#pragma unroll
        for (int i = tid; i < NTF * 8; i += THREADS) {
            const int t = i >> 3, c = i & 7;
            dst[i] = src[t * 16 + chunk * 8 + c];
        }
    }
    __syncthreads();

    const int lane = tid & 31;
    const char* fb = (const char*)xs + lane * 4;   // lane's 2-batch column
    const int wid = (blockIdx.x >> 1) * 32 + (tid >> 5);  // 0..2367 within chunk

    // static warp -> gene striding: uniform work, no atomics, no shfl
    for (int g = wid; g < NGENES; g += WARPS_PER_CHUNK) {
        // ---------------- layer 1: 4 nodes x 16 edges ----------------
        __half2 h1[4];
        const float4 b1v = __ldg((const float4*)(b1 + g * 4));
        const float bn[4] = {b1v.x, b1v.y, b1v.z, b1v.w};
#pragma unroll
        for (int n = 0; n < 4; n++) {
            const int4*  ip = (const int4*)(in1 + g * 64 + n * 16);
            const uint4* wp = (const uint4*)(g_w1h + g * 64 + n * 16);
            const int4 ia = __ldg(ip);
            const int4 ib = __ldg(ip + 1);
            const int4 ic = __ldg(ip + 2);
            const int4 id = __ldg(ip + 3);
            const uint4 wa = __ldg(wp);
            const uint4 wb = __ldg(wp + 1);
            float2 acc = make_float2(bn[n], bn[n]);
            edge_group(fb, ia, wa.x, wa.y, acc);
            edge_group(fb, ib, wa.z, wa.w, acc);
            edge_group(fb, ic, wb.x, wb.y, acc);
            edge_group(fb, id, wb.z, wb.w, acc);
            h1[n] = tanh_h2(acc);
        }

        // ---------------- layers 2+3 ----------------
        const uint4 w2v = __ldg((const uint4*)(g_w2h + g * 16));
        const uint4 w2u = __ldg((const uint4*)(g_w2h + g * 16) + 1);
        const float4 b2v = __ldg((const float4*)(b2 + g * 4));
        const float4 w3v = __ldg((const float4*)(w3 + g * 4));
        const float  yb  = __ldg(b3 + g);
        float2 y = make_float2(yb, yb);
        l23_node(h1, w2v.x, w2v.y, b2v.x, w3v.x, y);
        l23_node(h1, w2v.z, w2v.w, b2v.y, w3v.y, y);
        l23_node(h1, w2u.x, w2u.y, b2v.z, w3v.z, y);
        l23_node(h1, w2u.z, w2u.w, b2v.w, w3v.w, y);

        // coalesced gene-major store (float2 per lane, 256B per warp)
        *(float2*)&g_yT[g * BATCH + b0 + lane * 2] = y;
    }
}

extern "C" void kernel_launch(void* const* d_in, const int* in_sizes, int n_in,
                              void* d_out, int out_size) {
    const float* features = (const float*)d_in[0];
    const float* w1 = (const float*)d_in[1];
    const float* b1 = (const float*)d_in[2];
    const float* w2 = (const float*)d_in[3];
    const float* b2 = (const float*)d_in[4];
    const float* w3 = (const float*)d_in[5];
    const float* b3 = (const float*)d_in[6];
    const int* in1 = (const int*)d_in[8];
    float* out = (float*)d_out;

    cudaFuncSetAttribute(fused_kernel,
                         cudaFuncAttributeMaxDynamicSharedMemorySize, SMEM_BYTES);

    prep_kernel<<<910, 256>>>(features, w1, w2);
    fused_kernel<<<GRID, THREADS, SMEM_BYTES>>>(in1, b1, b2, w3, b3);
    transpose_out<<<dim3(NGENES / 32, BATCH / 32), dim3(32, 8)>>>(out);
}

// round 9
// speedup vs baseline: 1.2254x; 1.1758x over previous
#include <cuda_runtime.h>
#include <cuda_fp16.h>

#define BATCH 128
#define NTF 1024
#define NGENES 20000
#define NPAIRS (NGENES / 2)      // 10000 gene-pairs
#define NEDGE1 (NGENES * 64)     // 1,280,000 layer-1 edges
#define NW2 (NGENES * 16)        // 320,000 layer-2 weights
#define CHUNK 64                 // batch elements per block
#define THREADS 1024             // 32 warps
#define GRID 148                 // one wave, 74 blocks per chunk
#define WARPS_PER_CHUNK 2368     // 74 blocks * 32 warps
#define SMEM_BYTES (NTF * CHUNK * 2)  // 131072

// device scratch
__device__ __half g_xTh[NTF * BATCH];        // transposed fp16 features
__device__ unsigned short g_i16[NEDGE1];     // u16 edge indices
__device__ __half g_w1h[NEDGE1];             // fp16 layer-1 weights
__device__ __half g_w2h[NW2];                // fp16 layer-2 weights
__device__ float  g_yT[NGENES * BATCH];      // gene-major output

__device__ __forceinline__ unsigned int packh2(float a, float b) {
    const __half2 h = __float22half2_rn(make_float2(a, b));
    return *reinterpret_cast<const unsigned int*>(&h);
}
__device__ __forceinline__ unsigned int pack16(int a, int b) {
    return (unsigned int)a | ((unsigned int)b << 16);
}

// prep: [0,128) feature transpose; [128,441) edge idx+w1 tables; [441,520) w2
__global__ void prep_kernel(const float* __restrict__ f,
                            const float* __restrict__ w1,
                            const float* __restrict__ w2,
                            const int*   __restrict__ in1) {
    const int bid = blockIdx.x;
    if (bid < 128) {
        __shared__ float tile[32][33];
        const int tx = threadIdx.x & 31, ty = threadIdx.x >> 5;
        const int t0 = (bid & 31) * 32;   // TF base
        const int b0 = (bid >> 5) * 32;   // batch base
#pragma unroll
        for (int j = 0; j < 32; j += 8)
            tile[ty + j][tx] = f[(b0 + ty + j) * NTF + t0 + tx];
        __syncthreads();
#pragma unroll
        for (int j = 0; j < 32; j += 8)
            g_xTh[(t0 + ty + j) * BATCH + b0 + tx] = __float2half(tile[tx][ty + j]);
    } else if (bid < 441) {
        // 16 edges per thread: 4 independent int4 + 4 float4 LDG streams
        const int e = ((bid - 128) * 256 + threadIdx.x) * 16;
        if (e < NEDGE1) {
            const int4 i0 = __ldg((const int4*)(in1 + e));
            const int4 i1 = __ldg((const int4*)(in1 + e) + 1);
            const int4 i2 = __ldg((const int4*)(in1 + e) + 2);
            const int4 i3 = __ldg((const int4*)(in1 + e) + 3);
            const float4 a0 = __ldg((const float4*)(w1 + e));
            const float4 a1 = __ldg((const float4*)(w1 + e) + 1);
            const float4 a2 = __ldg((const float4*)(w1 + e) + 2);
            const float4 a3 = __ldg((const float4*)(w1 + e) + 3);
            uint4 ia, ib, wa, wb;
            ia.x = pack16(i0.x, i0.y); ia.y = pack16(i0.z, i0.w);
            ia.z = pack16(i1.x, i1.y); ia.w = pack16(i1.z, i1.w);
            ib.x = pack16(i2.x, i2.y); ib.y = pack16(i2.z, i2.w);
            ib.z = pack16(i3.x, i3.y); ib.w = pack16(i3.z, i3.w);
            wa.x = packh2(a0.x, a0.y); wa.y = packh2(a0.z, a0.w);
            wa.z = packh2(a1.x, a1.y); wa.w = packh2(a1.z, a1.w);
            wb.x = packh2(a2.x, a2.y); wb.y = packh2(a2.z, a2.w);
            wb.z = packh2(a3.x, a3.y); wb.w = packh2(a3.z, a3.w);
            *(uint4*)(g_i16 + e) = ia;
            *(uint4*)(g_i16 + e + 8) = ib;
            *(uint4*)(g_w1h + e) = wa;
            *(uint4*)(g_w1h + e + 8) = wb;
        }
    } else {
        const int e = ((bid - 441) * 256 + threadIdx.x) * 16;
        if (e < NW2) {
            const float4 a0 = __ldg((const float4*)(w2 + e));
            const float4 a1 = __ldg((const float4*)(w2 + e) + 1);
            const float4 a2 = __ldg((const float4*)(w2 + e) + 2);
            const float4 a3 = __ldg((const float4*)(w2 + e) + 3);
            uint4 wa, wb;
            wa.x = packh2(a0.x, a0.y); wa.y = packh2(a0.z, a0.w);
            wa.z = packh2(a1.x, a1.y); wa.w = packh2(a1.z, a1.w);
            wb.x = packh2(a2.x, a2.y); wb.y = packh2(a2.z, a2.w);
            wb.z = packh2(a3.x, a3.y); wb.w = packh2(a3.z, a3.w);
            *(uint4*)(g_w2h + e) = wa;
            *(uint4*)(g_w2h + e + 8) = wb;
        }
    }
}

// g_yT [NGENES][BATCH] -> out [BATCH][NGENES]
__global__ void transpose_out(float* __restrict__ out) {
    __shared__ float tile[32][33];
    const int tx = threadIdx.x, ty = threadIdx.y;
    const int g0 = blockIdx.x * 32;
    const int b0 = blockIdx.y * 32;
#pragma unroll
    for (int j = 0; j < 32; j += 8)
        tile[ty + j][tx] = g_yT[(g0 + ty + j) * BATCH + b0 + tx];
    __syncthreads();
#pragma unroll
    for (int j = 0; j < 32; j += 8)
        out[(b0 + ty + j) * NGENES + g0 + tx] = tile[tx][ty + j];
}

__device__ __forceinline__ __half2 u2h(unsigned int u) {
    return *reinterpret_cast<__half2*>(&u);
}
__device__ __forceinline__ float tanh_mufu(float x) {
    float y;
    asm("tanh.approx.f32 %0, %1;" : "=f"(y) : "f"(x));
    return y;
}
__device__ __forceinline__ __half2 tanh_h2(float2 a) {
    __half2 h = __float22half2_rn(a);
    unsigned int u = *reinterpret_cast<unsigned int*>(&h), r;
    asm("tanh.approx.f16x2 %0, %1;" : "=r"(r) : "r"(u));
    return u2h(r);
}

// 4 edges (2 packed index words), LDS.64 row gathers, fp16 chain, fp32 acc
__device__ __forceinline__ void edge_group(const char* fb, unsigned int e01,
                                           unsigned int e23, unsigned int wlo,
                                           unsigned int whi, float4& acc) {
    const uint2 x0 = *(const uint2*)(fb + ((e01 & 0xFFFFu) << 7));
    const uint2 x1 = *(const uint2*)(fb + ((e01 >> 16) << 7));
    const uint2 x2 = *(const uint2*)(fb + ((e23 & 0xFFFFu) << 7));
    const uint2 x3 = *(const uint2*)(fb + ((e23 >> 16) << 7));
    __half2 alo = __hmul2(__low2half2(u2h(wlo)),  u2h(x0.x));
    __half2 ahi = __hmul2(__low2half2(u2h(wlo)),  u2h(x0.y));
    alo = __hfma2(__high2half2(u2h(wlo)), u2h(x1.x), alo);
    ahi = __hfma2(__high2half2(u2h(wlo)), u2h(x1.y), ahi);
    alo = __hfma2(__low2half2(u2h(whi)),  u2h(x2.x), alo);
    ahi = __hfma2(__low2half2(u2h(whi)),  u2h(x2.y), ahi);
    alo = __hfma2(__high2half2(u2h(whi)), u2h(x3.x), alo);
    ahi = __hfma2(__high2half2(u2h(whi)), u2h(x3.y), ahi);
    const float2 flo = __half22float2(alo);
    const float2 fhi = __half22float2(ahi);
    acc.x += flo.x; acc.y += flo.y; acc.z += fhi.x; acc.w += fhi.y;
}

// layer-2 node (fp16 MAC) + fp32 tanh + fp32 layer-3 accumulate, 4 batches
__device__ __forceinline__ void l23_node(const __half2* h1lo, const __half2* h1hi,
                                         unsigned int wlo, unsigned int whi,
                                         float b2o, float w3o, float4& y) {
    const __half2 bb = __half2half2(__float2half(b2o));
    __half2 slo = bb, shi = bb;
    slo = __hfma2(__low2half2(u2h(wlo)),  h1lo[0], slo);
    shi = __hfma2(__low2half2(u2h(wlo)),  h1hi[0], shi);
    slo = __hfma2(__high2half2(u2h(wlo)), h1lo[1], slo);
    shi = __hfma2(__high2half2(u2h(wlo)), h1hi[1], shi);
    slo = __hfma2(__low2half2(u2h(whi)),  h1lo[2], slo);
    shi = __hfma2(__low2half2(u2h(whi)),  h1hi[2], shi);
    slo = __hfma2(__high2half2(u2h(whi)), h1lo[3], slo);
    shi = __hfma2(__high2half2(u2h(whi)), h1hi[3], shi);
    const float2 a = __half22float2(slo);
    const float2 b = __half22float2(shi);
    y.x = fmaf(w3o, tanh_mufu(a.x), y.x);
    y.y = fmaf(w3o, tanh_mufu(a.y), y.y);
    y.z = fmaf(w3o, tanh_mufu(b.x), y.z);
    y.w = fmaf(w3o, tanh_mufu(b.y), y.w);
}

__global__ void __launch_bounds__(THREADS, 1) fused_kernel(
    const float* __restrict__ b1, const float* __restrict__ b2,
    const float* __restrict__ w3, const float* __restrict__ b3)
{
    extern __shared__ unsigned int xs[];   // [NTF][32] uint -> 128B fp16 rows
    const int tid = threadIdx.x;
    const int chunk = blockIdx.x & 1;      // 148 blocks -> 74 per chunk
    const int b0 = chunk * CHUNK;

    // fill feature slice (rows of 64 fp16 = 8 uint4)
    {
        const uint4* src = (const uint4*)g_xTh;  // global row = 16 uint4
        uint4* dst = (uint4*)xs;
#pragma unroll
        for (int i = tid; i < NTF * 8; i += THREADS) {
            const int t = i >> 3, c = i & 7;
            dst[i] = src[t * 16 + chunk * 8 + c];
        }
    }
    __syncthreads();

    const int lane = tid & 31;
    const int gl   = lane >> 4;     // gene within pair (0..1)
    const int bsub = lane & 15;     // batch quad -> batches b0+bsub*4 .. +3
    const char* fb = (const char*)xs + bsub * 8;   // lane's 4-batch column
    const int wid = (blockIdx.x >> 1) * 32 + (tid >> 5);  // 0..2367 in chunk

    for (int p = wid; p < NPAIRS; p += WARPS_PER_CHUNK) {
        const int g = p * 2 + gl;
        const uint4* ip = (const uint4*)(g_i16 + (size_t)g * 64);
        const uint4* wp = (const uint4*)(g_w1h + (size_t)g * 64);

        // ---- layer 1: 4 nodes x 16 edges, node-level double buffering ----
        uint4 ca = __ldg(ip), cb = __ldg(ip + 1);
        uint4 cwa = __ldg(wp), cwb = __ldg(wp + 1);
        const float4 b1v = __ldg((const float4*)(b1 + g * 4));
        const float bn[4] = {b1v.x, b1v.y, b1v.z, b1v.w};
        __half2 h1lo[4], h1hi[4];
#pragma unroll
        for (int n = 0; n < 4; n++) {
            uint4 na, nb, nwa, nwb;
            if (n < 3) {   // prefetch next node's metadata before computing
                na  = __ldg(ip + 2 * n + 2); nb  = __ldg(ip + 2 * n + 3);
                nwa = __ldg(wp + 2 * n + 2); nwb = __ldg(wp + 2 * n + 3);
            }
            float4 acc = make_float4(bn[n], bn[n], bn[n], bn[n]);
            edge_group(fb, ca.x, ca.y, cwa.x, cwa.y, acc);
            edge_group(fb, ca.z, ca.w, cwa.z, cwa.w, acc);
            edge_group(fb, cb.x, cb.y, cwb.x, cwb.y, acc);
            edge_group(fb, cb.z, cb.w, cwb.z, cwb.w, acc);
            h1lo[n] = tanh_h2(make_float2(acc.x, acc.y));
            h1hi[n] = tanh_h2(make_float2(acc.z, acc.w));
            if (n < 3) { ca = na; cb = nb; cwa = nwa; cwb = nwb; }
        }

        // ---------------- layers 2+3 ----------------
        const uint4 w2a = __ldg((const uint4*)(g_w2h + (size_t)g * 16));
        const uint4 w2b = __ldg((const uint4*)(g_w2h + (size_t)g * 16) + 1);
        const float4 b2v = __ldg((const float4*)(b2 + g * 4));
        const float4 w3v = __ldg((const float4*)(w3 + g * 4));
        const float  yb  = __ldg(b3 + g);
        float4 y = make_float4(yb, yb, yb, yb);
        l23_node(h1lo, h1hi, w2a.x, w2a.y, b2v.x, w3v.x, y);
        l23_node(h1lo, h1hi, w2a.z, w2a.w, b2v.y, w3v.y, y);
        l23_node(h1lo, h1hi, w2b.x, w2b.y, b2v.z, w3v.z, y);
        l23_node(h1lo, h1hi, w2b.z, w2b.w, b2v.w, w3v.w, y);

        // coalesced gene-major store (float4 per lane)
        *(float4*)&g_yT[(size_t)g * BATCH + b0 + bsub * 4] = y;
    }
}

extern "C" void kernel_launch(void* const* d_in, const int* in_sizes, int n_in,
                              void* d_out, int out_size) {
    const float* features = (const float*)d_in[0];
    const float* w1 = (const float*)d_in[1];
    const float* b1 = (const float*)d_in[2];
    const float* w2 = (const float*)d_in[3];
    const float* b2 = (const float*)d_in[4];
    const float* w3 = (const float*)d_in[5];
    const float* b3 = (const float*)d_in[6];
    const int* in1 = (const int*)d_in[8];
    float* out = (float*)d_out;

    cudaFuncSetAttribute(fused_kernel,
                         cudaFuncAttributeMaxDynamicSharedMemorySize, SMEM_BYTES);

    prep_kernel<<<520, 256>>>(features, w1, w2, in1);
    fused_kernel<<<GRID, THREADS, SMEM_BYTES>>>(b1, b2, w3, b3);
    transpose_out<<<dim3(NGENES / 32, BATCH / 32), dim3(32, 8)>>>(out);
}